// round 13
// baseline (speedup 1.0000x reference)
#include <cuda_runtime.h>
#include <cuda_bf16.h>
#include <cstdint>

#define N_NODES 100000
#define N_EDGES 3200000
#define IN_DIM  512
#define HID     64
#define OUT_DIM 5

#define SB 1024
#define NBLK ((N_NODES + SB - 1) / SB)   // 98

#define NCHUNK 4
#define CHUNK  (N_NODES / NCHUNK)        // 25000

// Scratch (allocation-free rule): __device__ globals, device-code refs only.
// Dataflow: hA =x@W1=> (pull1) => hB =relu@W2=> hC => (pull2+FC) => out
__device__ __align__(16) float g_dinv[N_NODES];
__device__ __align__(16) float g_hA[(size_t)N_NODES * HID];
__device__ __align__(16) float g_hB[(size_t)N_NODES * HID];
__device__ __align__(16) float g_hC[(size_t)N_NODES * HID];
// CSR (dst-binned), rebuilt each launch, shared by both layers.
__device__ int  g_cnt[N_NODES];
__device__ int  g_rowptr[N_NODES + 1];
__device__ int  g_cursor[N_NODES];
__device__ int  g_bsum[NBLK];
__device__ __align__(8) int2 g_epack[N_EDGES];   // {src, bitcast(norm)}

// ---------------- degree + incoming-count ----------------

__global__ void k_init() {
    int i = blockIdx.x * blockDim.x + threadIdx.x;
    if (i < N_NODES) { g_dinv[i] = 1.0f; g_cnt[i] = 0; }
}

__global__ void k_accum_deg(const int* __restrict__ ei,
                            const float* __restrict__ ew) {
    int e = blockIdx.x * blockDim.x + threadIdx.x;
    if (e < N_EDGES) {
        int d = ei[N_EDGES + e];
        atomicAdd(&g_dinv[d], ew[e]);
        atomicAdd(&g_cnt[d], 1);
    }
}

__global__ void k_rsqrt() {
    int i = blockIdx.x * blockDim.x + threadIdx.x;
    if (i < N_NODES) g_dinv[i] = rsqrtf(g_dinv[i]);
}

// ---------------- multi-block 3-phase prefix scan ----------------

__global__ void __launch_bounds__(SB) k_scan1() {
    __shared__ int ws[32];
    int tid = threadIdx.x, lane = tid & 31, wid = tid >> 5;
    int i = blockIdx.x * SB + tid;
    int v = (i < N_NODES) ? g_cnt[i] : 0;
    int x = v;
#pragma unroll
    for (int o = 1; o < 32; o <<= 1) {
        int y = __shfl_up_sync(~0u, x, o);
        if (lane >= o) x += y;
    }
    if (lane == 31) ws[wid] = x;
    __syncthreads();
    if (wid == 0) {
        int w = ws[lane];
#pragma unroll
        for (int o = 1; o < 32; o <<= 1) {
            int y = __shfl_up_sync(~0u, w, o);
            if (lane >= o) w += y;
        }
        ws[lane] = w;
    }
    __syncthreads();
    int incl = x + (wid > 0 ? ws[wid - 1] : 0);
    if (i < N_NODES) g_rowptr[i + 1] = incl;
    if (tid == SB - 1) g_bsum[blockIdx.x] = incl;
}

__global__ void k_scan2() {
    int lane = threadIdx.x;
    int carry = 0;
    for (int base = 0; base < NBLK; base += 32) {
        int v = (base + lane < NBLK) ? g_bsum[base + lane] : 0;
        int x = v;
#pragma unroll
        for (int o = 1; o < 32; o <<= 1) {
            int y = __shfl_up_sync(~0u, x, o);
            if (lane >= o) x += y;
        }
        if (base + lane < NBLK) g_bsum[base + lane] = x - v + carry;
        carry += __shfl_sync(~0u, x, 31);
    }
}

__global__ void __launch_bounds__(SB) k_scan3() {
    int i = blockIdx.x * SB + threadIdx.x;
    if (i >= N_NODES) return;
    int off = g_bsum[i >> 10];
    int r = g_rowptr[i + 1] + off;
    g_rowptr[i + 1] = r;
    g_cursor[i] = r - g_cnt[i];
    if (i == 0) g_rowptr[0] = 0;
}

// ---------------- CSR fill ----------------

__global__ void k_fill(const int* __restrict__ ei, const float* __restrict__ ew) {
    int e = blockIdx.x * blockDim.x + threadIdx.x;
    if (e >= N_EDGES) return;
    int s = ei[e];
    int d = ei[N_EDGES + e];
    float nm = g_dinv[s] * ew[e] * g_dinv[d];
    int pos = atomicAdd(&g_cursor[d], 1);
    g_epack[pos] = make_int2(s, __float_as_int(nm));
}

// ---------------- bf16 split helpers ----------------

__device__ __forceinline__ void split_bf2(float v0, float v1,
                                          uint32_t& h, uint32_t& l) {
    __nv_bfloat16 b0 = __float2bfloat16(v0);
    __nv_bfloat16 b1 = __float2bfloat16(v1);
    __nv_bfloat162 hp = __halves2bfloat162(b0, b1);   // b0 in low 16 bits
    h = *reinterpret_cast<uint32_t*>(&hp);
    float r0 = v0 - __bfloat162float(b0);
    float r1 = v1 - __bfloat162float(b1);
    asm("cvt.rn.bf16x2.f32 %0, %1, %2;" : "=r"(l) : "f"(r1), "f"(r0));
}

__device__ __forceinline__ void mma_bf16(float* c, const uint32_t* a, const uint32_t* b) {
    asm volatile(
        "mma.sync.aligned.m16n8k16.row.col.f32.bf16.bf16.f32 "
        "{%0,%1,%2,%3}, {%4,%5,%6,%7}, {%8,%9}, {%0,%1,%2,%3};"
        : "+f"(c[0]), "+f"(c[1]), "+f"(c[2]), "+f"(c[3])
        : "r"(a[0]), "r"(a[1]), "r"(a[2]), "r"(a[3]), "r"(b[0]), "r"(b[1]));
}

__device__ __forceinline__ void cp16(uint32_t dst, const void* src, bool valid) {
    asm volatile("cp.async.cg.shared.global [%0], [%1], 16, %2;"
                 :: "r"(dst), "l"(src), "r"(valid ? 16 : 0) : "memory");
}

// ------- 3xBF16 tensor-core GEMM (layer 1): g_hA = x @ W1, K=512 -------

#define APITCH 20
#define BPITCH 72

__global__ void __launch_bounds__(256)
k_gemm_bf16(const float* __restrict__ A, const float* __restrict__ B, int K) {
    __shared__ float As[2][128 * APITCH];
    __shared__ float Bs[2][16 * BPITCH];

    const int M = N_NODES;
    int tid  = threadIdx.x;
    int wid  = tid >> 5;
    int lane = tid & 31;
    int wm = wid >> 1, wn = wid & 1;
    int qr = lane >> 2, qc = lane & 3;
    int rowBase = blockIdx.x * 128;

    int ar0 = tid >> 2,         ac0 = (tid & 3) * 4;
    int ar1 = (tid >> 2) + 64,  ac1 = ac0;
    int brr = tid >> 4,         bcc = (tid & 15) * 4;

    uint32_t sA0[2], sA1[2], sB0[2];
#pragma unroll
    for (int b = 0; b < 2; b++) {
        sA0[b] = (uint32_t)__cvta_generic_to_shared(&As[b][ar0 * APITCH + ac0]);
        sA1[b] = (uint32_t)__cvta_generic_to_shared(&As[b][ar1 * APITCH + ac1]);
        sB0[b] = (uint32_t)__cvta_generic_to_shared(&Bs[b][brr * BPITCH + bcc]);
    }

    auto loadTiles = [&](int k0, int buf) {
        int g0 = rowBase + ar0, g1 = rowBase + ar1;
        bool v0 = g0 < M, v1 = g1 < M;
        cp16(sA0[buf], &A[(size_t)(v0 ? g0 : 0) * K + k0 + ac0], v0);
        cp16(sA1[buf], &A[(size_t)(v1 ? g1 : 0) * K + k0 + ac1], v1);
        cp16(sB0[buf], &B[(size_t)(k0 + brr) * HID + bcc], true);
        asm volatile("cp.async.commit_group;" ::: "memory");
    };

    float acc[2][4][4];
#pragma unroll
    for (int mt = 0; mt < 2; mt++)
#pragma unroll
        for (int nt = 0; nt < 4; nt++)
#pragma unroll
            for (int i = 0; i < 4; i++) acc[mt][nt][i] = 0.0f;

    const int NIT = K / 16;   // 32
    loadTiles(0, 0);

    for (int it = 0; it < NIT; it++) {
        int buf = it & 1;
        if (it + 1 < NIT) {
            loadTiles((it + 1) * 16, buf ^ 1);
            asm volatile("cp.async.wait_group 1;" ::: "memory");
        } else {
            asm volatile("cp.async.wait_group 0;" ::: "memory");
        }
        __syncthreads();

        const float* as = As[buf];
        const float* bs = Bs[buf];

        uint32_t fah[2][4], fal[2][4];
#pragma unroll
        for (int mt = 0; mt < 2; mt++) {
            int r0 = wm * 32 + mt * 16 + qr;
            int c0 = 2 * qc;
            float2 p0 = *reinterpret_cast<const float2*>(&as[r0 * APITCH + c0]);
            float2 p1 = *reinterpret_cast<const float2*>(&as[(r0 + 8) * APITCH + c0]);
            float2 p2 = *reinterpret_cast<const float2*>(&as[r0 * APITCH + c0 + 8]);
            float2 p3 = *reinterpret_cast<const float2*>(&as[(r0 + 8) * APITCH + c0 + 8]);
            split_bf2(p0.x, p0.y, fah[mt][0], fal[mt][0]);
            split_bf2(p1.x, p1.y, fah[mt][1], fal[mt][1]);
            split_bf2(p2.x, p2.y, fah[mt][2], fal[mt][2]);
            split_bf2(p3.x, p3.y, fah[mt][3], fal[mt][3]);
        }
        uint32_t fbh[4][2], fbl[4][2];
#pragma unroll
        for (int nt = 0; nt < 4; nt++) {
            int col = wn * 32 + nt * 8 + qr;
            float v0 = bs[(2 * qc) * BPITCH + col];
            float v1 = bs[(2 * qc + 1) * BPITCH + col];
            float v2 = bs[(2 * qc + 8) * BPITCH + col];
            float v3 = bs[(2 * qc + 9) * BPITCH + col];
            split_bf2(v0, v1, fbh[nt][0], fbl[nt][0]);
            split_bf2(v2, v3, fbh[nt][1], fbl[nt][1]);
        }
#pragma unroll
        for (int mt = 0; mt < 2; mt++)
#pragma unroll
            for (int nt = 0; nt < 4; nt++) {
                mma_bf16(acc[mt][nt], fah[mt], fbh[nt]);
                mma_bf16(acc[mt][nt], fah[mt], fbl[nt]);
                mma_bf16(acc[mt][nt], fal[mt], fbh[nt]);
            }
        __syncthreads();
    }

#pragma unroll
    for (int mt = 0; mt < 2; mt++) {
#pragma unroll
        for (int nt = 0; nt < 4; nt++) {
            int r  = rowBase + wm * 32 + mt * 16 + qr;
            int cc = wn * 32 + nt * 8 + qc * 2;
            if (r < M)
                *reinterpret_cast<float2*>(&g_hA[(size_t)r * HID + cc]) =
                    make_float2(acc[mt][nt][0], acc[mt][nt][1]);
            if (r + 8 < M)
                *reinterpret_cast<float2*>(&g_hA[(size_t)(r + 8) * HID + cc]) =
                    make_float2(acc[mt][nt][2], acc[mt][nt][3]);
        }
    }
}

// ------- FFMA GEMM (layer 2, K=64), row-chunked: g_hC = relu(g_hB) @ W2 -------
// rowEnd clamp: no block reads g_hB rows beyond its chunk's dependency.

__global__ void __launch_bounds__(256)
k_gemm64(const float* __restrict__ B, int rowOffset, int rowEnd) {
    const int BM = 128, BN = 64, BK = 32, TM = 8, TN = 4, K = HID;
    __shared__ float As[BK][BM];
    __shared__ float Bs[BK][BN];

    const float* A = g_hB;

    int tid = threadIdx.x;
    int tx = tid & 15;
    int ty = tid >> 4;
    int rowBase = rowOffset + blockIdx.x * BM;

    float acc[TM][TN];
#pragma unroll
    for (int m = 0; m < TM; m++)
#pragma unroll
        for (int n = 0; n < TN; n++) acc[m][n] = 0.0f;

    for (int k0 = 0; k0 < K; k0 += BK) {
#pragma unroll
        for (int i = 0; i < 4; i++) {
            int idx = tid + i * 256;
            int r   = idx >> 3;
            int k4  = idx & 7;
            int grow = rowBase + r;
            float4 v = make_float4(0.f, 0.f, 0.f, 0.f);
            if (grow < rowEnd)
                v = *reinterpret_cast<const float4*>(&A[(size_t)grow * K + k0 + k4 * 4]);
            v.x = fmaxf(v.x, 0.f); v.y = fmaxf(v.y, 0.f);
            v.z = fmaxf(v.z, 0.f); v.w = fmaxf(v.w, 0.f);
            As[k4 * 4 + 0][r] = v.x;
            As[k4 * 4 + 1][r] = v.y;
            As[k4 * 4 + 2][r] = v.z;
            As[k4 * 4 + 3][r] = v.w;
        }
#pragma unroll
        for (int i = 0; i < 2; i++) {
            int idx = tid + i * 256;
            int r = idx >> 4;
            int c4 = idx & 15;
            *reinterpret_cast<float4*>(&Bs[r][c4 * 4]) =
                *reinterpret_cast<const float4*>(&B[(size_t)(k0 + r) * BN + c4 * 4]);
        }
        __syncthreads();

#pragma unroll
        for (int k = 0; k < BK; k++) {
            float a[TM], b[TN];
#pragma unroll
            for (int m = 0; m < TM; m++) a[m] = As[k][ty * TM + m];
#pragma unroll
            for (int n = 0; n < TN; n++) b[n] = Bs[k][tx * TN + n];
#pragma unroll
            for (int m = 0; m < TM; m++)
#pragma unroll
                for (int n = 0; n < TN; n++) acc[m][n] = fmaf(a[m], b[n], acc[m][n]);
        }
        __syncthreads();
    }

#pragma unroll
    for (int m = 0; m < TM; m++) {
        int grow = rowBase + ty * TM + m;
        if (grow < rowEnd) {
            float4 v = make_float4(acc[m][0], acc[m][1], acc[m][2], acc[m][3]);
            *reinterpret_cast<float4*>(&g_hC[(size_t)grow * BN + tx * TN]) = v;
        }
    }
}

// -------- pull aggregation: one warp per dst row, fixed-trip unrolled gather --------
// pull1 (FUSE_FC=false): reads g_hA, writes g_hB.
// pull2 (FUSE_FC=true):  reads g_hC, applies ReLU + FC, writes out.

template <bool FUSE_FC>
__global__ void __launch_bounds__(256)
k_pull(const float* __restrict__ bias, const float* __restrict__ Wfc,
       const float* __restrict__ bfc, float* __restrict__ out, int rowOffset) {
    int lane = threadIdx.x & 31;
    int row = rowOffset + blockIdx.x * 8 + (threadIdx.x >> 5);
    if (row >= N_NODES) return;

    const float* H = FUSE_FC ? g_hC : g_hA;

    float di = g_dinv[row];
    float c = di * di;
    const float* hr = &H[(size_t)row * HID];
    float a0 = fmaf(hr[lane],      c, bias[lane]);
    float a1 = fmaf(hr[lane + 32], c, bias[lane + 32]);

    int start = g_rowptr[row];
    int end   = g_rowptr[row + 1];
    for (int i = start; i < end; i += 32) {
        int2 pk = make_int2(0, 0);
        if (i + lane < end) pk = g_epack[i + lane];
#pragma unroll
        for (int j = 0; j < 32; j++) {
            int   s  = __shfl_sync(~0u, pk.x, j);
            float nm = __int_as_float(__shfl_sync(~0u, pk.y, j));
            const float* hs = &H[(size_t)s * HID];
            a0 = fmaf(hs[lane],      nm, a0);
            a1 = fmaf(hs[lane + 32], nm, a1);
        }
    }

    if (!FUSE_FC) {
        g_hB[(size_t)row * HID + lane]      = a0;
        g_hB[(size_t)row * HID + lane + 32] = a1;
    } else {
        a0 = fmaxf(a0, 0.f);
        a1 = fmaxf(a1, 0.f);
        float res[OUT_DIM];
#pragma unroll
        for (int k = 0; k < OUT_DIM; k++) {
            float p = a0 * __ldg(&Wfc[lane * OUT_DIM + k]) +
                      a1 * __ldg(&Wfc[(lane + 32) * OUT_DIM + k]);
#pragma unroll
            for (int o = 16; o > 0; o >>= 1) p += __shfl_xor_sync(~0u, p, o);
            res[k] = p;
        }
        if (lane < OUT_DIM)
            out[(size_t)row * OUT_DIM + lane] = res[lane] + bfc[lane];
    }
}

// ---------------- launcher ----------------
// DAG: CSR-build || GEMM1 (fork/join); pull1(c) pipeline-feeds gemm64(c)
// on s1 (separate hC output buffer: no aliasing with pull1's hA gathers);
// join; pull2+FC.

extern "C" void kernel_launch(void* const* d_in, const int* in_sizes, int n_in,
                              void* d_out, int out_size) {
    const float* x   = (const float*)d_in[0];
    const int*   ei  = (const int*)d_in[1];    // int32 (JAX x64 disabled)
    const float* ew  = (const float*)d_in[2];
    const float* W1  = (const float*)d_in[3];
    const float* b1  = (const float*)d_in[4];
    const float* W2  = (const float*)d_in[5];
    const float* b2  = (const float*)d_in[6];
    const float* Wfc = (const float*)d_in[7];
    const float* bfc = (const float*)d_in[8];
    float* out = (float*)d_out;

    static cudaStream_t s1 = nullptr;
    static cudaEvent_t evFork = nullptr, evJoin = nullptr, evG = nullptr;
    static cudaEvent_t evP[NCHUNK] = {};
    if (!s1) {
        cudaStreamCreateWithFlags(&s1, cudaStreamNonBlocking);
        cudaEventCreateWithFlags(&evFork, cudaEventDisableTiming);
        cudaEventCreateWithFlags(&evJoin, cudaEventDisableTiming);
        cudaEventCreateWithFlags(&evG, cudaEventDisableTiming);
        for (int i = 0; i < NCHUNK; i++)
            cudaEventCreateWithFlags(&evP[i], cudaEventDisableTiming);
    }

    const int T = 256;
    int gbN     = (N_NODES + T - 1) / T;
    int gbE     = (N_EDGES + T - 1) / T;
    int gbGemm  = (N_NODES + 127) / 128;
    int gbGemmC = (CHUNK + 127) / 128;
    int gbPull  = (N_NODES + 7) / 8;
    int gbPullC = (CHUNK + 7) / 8;

    // Fork: GEMM1 on s1, CSR build on the main (capture) stream.
    cudaEventRecord(evFork, 0);
    cudaStreamWaitEvent(s1, evFork, 0);
    k_gemm_bf16<<<gbGemm, T, 0, s1>>>(x, W1, IN_DIM);
    cudaEventRecord(evJoin, s1);

    k_init<<<gbN, T>>>();
    k_accum_deg<<<gbE, T>>>(ei, ew);
    k_rsqrt<<<gbN, T>>>();
    k_scan1<<<NBLK, SB>>>();
    k_scan2<<<1, 32>>>();
    k_scan3<<<NBLK, SB>>>();
    k_fill<<<gbE, T>>>(ei, ew);

    // Join: pull1 needs both hA (s1) and the CSR (main stream).
    cudaStreamWaitEvent((cudaStream_t)0, evJoin, 0);

    // Chunk pipeline: pull1(c) on stream 0 -> gemm64(c) on s1.
    // gemm64 reads only hB rows [c*CHUNK, chunk end) (clamped) and writes
    // hC, which pull1 never touches. No aliasing, no boundary overreads.
    for (int c = 0; c < NCHUNK; c++) {
        int r0 = c * CHUNK;
        int r1 = (c == NCHUNK - 1) ? N_NODES : (c + 1) * CHUNK;
        k_pull<false><<<gbPullC, T>>>(b1, nullptr, nullptr, nullptr, r0);
        cudaEventRecord(evP[c], 0);
        cudaStreamWaitEvent(s1, evP[c], 0);
        k_gemm64<<<gbGemmC, T, 0, s1>>>(W2, r0, r1);
    }
    cudaEventRecord(evG, s1);
    cudaStreamWaitEvent((cudaStream_t)0, evG, 0);

    // layer 2 aggregation + fused FC (reads hC)
    k_pull<true><<<gbPull, T>>>(b2, Wfc, bfc, out, 0);
}

// round 14
// speedup vs baseline: 1.0077x; 1.0077x over previous
#include <cuda_runtime.h>
#include <cuda_bf16.h>
#include <cstdint>

#define N_NODES 100000
#define N_EDGES 3200000
#define IN_DIM  512
#define HID     64
#define OUT_DIM 5

#define SB 1024
#define NBLK ((N_NODES + SB - 1) / SB)   // 98

#define NCHUNK 4
#define CHUNK  (N_NODES / NCHUNK)        // 25000

// Scratch (allocation-free rule): __device__ globals, device-code refs only.
// Dataflow: hA =x@W1=> (pull1) => hB =relu@W2=> hC => (pull2+FC) => out
__device__ __align__(16) float g_dinv[N_NODES];
__device__ __align__(16) float g_hA[(size_t)N_NODES * HID];
__device__ __align__(16) float g_hB[(size_t)N_NODES * HID];
__device__ __align__(16) float g_hC[(size_t)N_NODES * HID];
// CSR (dst-binned), rebuilt each launch, shared by both layers.
__device__ int  g_cnt[N_NODES];
__device__ int  g_rowptr[N_NODES + 1];
__device__ int  g_cursor[N_NODES];
__device__ int  g_bsum[NBLK];
__device__ __align__(8) int2 g_epack[N_EDGES];   // {src, bitcast(norm)}

// ---------------- degree + incoming-count ----------------

__global__ void k_init() {
    int i = blockIdx.x * blockDim.x + threadIdx.x;
    if (i < N_NODES) { g_dinv[i] = 1.0f; g_cnt[i] = 0; }
}

__global__ void k_accum_deg(const int* __restrict__ ei,
                            const float* __restrict__ ew) {
    int e = blockIdx.x * blockDim.x + threadIdx.x;
    if (e < N_EDGES) {
        int d = ei[N_EDGES + e];
        atomicAdd(&g_dinv[d], ew[e]);
        atomicAdd(&g_cnt[d], 1);
    }
}

__global__ void k_rsqrt() {
    int i = blockIdx.x * blockDim.x + threadIdx.x;
    if (i < N_NODES) g_dinv[i] = rsqrtf(g_dinv[i]);
}

// ---------------- multi-block 3-phase prefix scan ----------------

__global__ void __launch_bounds__(SB) k_scan1() {
    __shared__ int ws[32];
    int tid = threadIdx.x, lane = tid & 31, wid = tid >> 5;
    int i = blockIdx.x * SB + tid;
    int v = (i < N_NODES) ? g_cnt[i] : 0;
    int x = v;
#pragma unroll
    for (int o = 1; o < 32; o <<= 1) {
        int y = __shfl_up_sync(~0u, x, o);
        if (lane >= o) x += y;
    }
    if (lane == 31) ws[wid] = x;
    __syncthreads();
    if (wid == 0) {
        int w = ws[lane];
#pragma unroll
        for (int o = 1; o < 32; o <<= 1) {
            int y = __shfl_up_sync(~0u, w, o);
            if (lane >= o) w += y;
        }
        ws[lane] = w;
    }
    __syncthreads();
    int incl = x + (wid > 0 ? ws[wid - 1] : 0);
    if (i < N_NODES) g_rowptr[i + 1] = incl;
    if (tid == SB - 1) g_bsum[blockIdx.x] = incl;
}

__global__ void k_scan2() {
    int lane = threadIdx.x;
    int carry = 0;
    for (int base = 0; base < NBLK; base += 32) {
        int v = (base + lane < NBLK) ? g_bsum[base + lane] : 0;
        int x = v;
#pragma unroll
        for (int o = 1; o < 32; o <<= 1) {
            int y = __shfl_up_sync(~0u, x, o);
            if (lane >= o) x += y;
        }
        if (base + lane < NBLK) g_bsum[base + lane] = x - v + carry;
        carry += __shfl_sync(~0u, x, 31);
    }
}

__global__ void __launch_bounds__(SB) k_scan3() {
    int i = blockIdx.x * SB + threadIdx.x;
    if (i >= N_NODES) return;
    int off = g_bsum[i >> 10];
    int r = g_rowptr[i + 1] + off;
    g_rowptr[i + 1] = r;
    g_cursor[i] = r - g_cnt[i];
    if (i == 0) g_rowptr[0] = 0;
}

// ---------------- CSR fill ----------------

__global__ void k_fill(const int* __restrict__ ei, const float* __restrict__ ew) {
    int e = blockIdx.x * blockDim.x + threadIdx.x;
    if (e >= N_EDGES) return;
    int s = ei[e];
    int d = ei[N_EDGES + e];
    float nm = g_dinv[s] * ew[e] * g_dinv[d];
    int pos = atomicAdd(&g_cursor[d], 1);
    g_epack[pos] = make_int2(s, __float_as_int(nm));
}

// ---------------- bf16 split helpers ----------------

__device__ __forceinline__ void split_bf2(float v0, float v1,
                                          uint32_t& h, uint32_t& l) {
    __nv_bfloat16 b0 = __float2bfloat16(v0);
    __nv_bfloat16 b1 = __float2bfloat16(v1);
    __nv_bfloat162 hp = __halves2bfloat162(b0, b1);   // b0 in low 16 bits
    h = *reinterpret_cast<uint32_t*>(&hp);
    float r0 = v0 - __bfloat162float(b0);
    float r1 = v1 - __bfloat162float(b1);
    asm("cvt.rn.bf16x2.f32 %0, %1, %2;" : "=r"(l) : "f"(r1), "f"(r0));
}

__device__ __forceinline__ void mma_bf16(float* c, const uint32_t* a, const uint32_t* b) {
    asm volatile(
        "mma.sync.aligned.m16n8k16.row.col.f32.bf16.bf16.f32 "
        "{%0,%1,%2,%3}, {%4,%5,%6,%7}, {%8,%9}, {%0,%1,%2,%3};"
        : "+f"(c[0]), "+f"(c[1]), "+f"(c[2]), "+f"(c[3])
        : "r"(a[0]), "r"(a[1]), "r"(a[2]), "r"(a[3]), "r"(b[0]), "r"(b[1]));
}

__device__ __forceinline__ void cp16(uint32_t dst, const void* src, bool valid) {
    asm volatile("cp.async.cg.shared.global [%0], [%1], 16, %2;"
                 :: "r"(dst), "l"(src), "r"(valid ? 16 : 0) : "memory");
}

// ------- 3xBF16 tensor-core GEMM (layer 1): g_hA = x @ W1, K=512 -------

#define APITCH 20
#define BPITCH 72

__global__ void __launch_bounds__(256)
k_gemm_bf16(const float* __restrict__ A, const float* __restrict__ B, int K) {
    __shared__ float As[2][128 * APITCH];
    __shared__ float Bs[2][16 * BPITCH];

    const int M = N_NODES;
    int tid  = threadIdx.x;
    int wid  = tid >> 5;
    int lane = tid & 31;
    int wm = wid >> 1, wn = wid & 1;
    int qr = lane >> 2, qc = lane & 3;
    int rowBase = blockIdx.x * 128;

    int ar0 = tid >> 2,         ac0 = (tid & 3) * 4;
    int ar1 = (tid >> 2) + 64,  ac1 = ac0;
    int brr = tid >> 4,         bcc = (tid & 15) * 4;

    uint32_t sA0[2], sA1[2], sB0[2];
#pragma unroll
    for (int b = 0; b < 2; b++) {
        sA0[b] = (uint32_t)__cvta_generic_to_shared(&As[b][ar0 * APITCH + ac0]);
        sA1[b] = (uint32_t)__cvta_generic_to_shared(&As[b][ar1 * APITCH + ac1]);
        sB0[b] = (uint32_t)__cvta_generic_to_shared(&Bs[b][brr * BPITCH + bcc]);
    }

    auto loadTiles = [&](int k0, int buf) {
        int g0 = rowBase + ar0, g1 = rowBase + ar1;
        bool v0 = g0 < M, v1 = g1 < M;
        cp16(sA0[buf], &A[(size_t)(v0 ? g0 : 0) * K + k0 + ac0], v0);
        cp16(sA1[buf], &A[(size_t)(v1 ? g1 : 0) * K + k0 + ac1], v1);
        cp16(sB0[buf], &B[(size_t)(k0 + brr) * HID + bcc], true);
        asm volatile("cp.async.commit_group;" ::: "memory");
    };

    float acc[2][4][4];
#pragma unroll
    for (int mt = 0; mt < 2; mt++)
#pragma unroll
        for (int nt = 0; nt < 4; nt++)
#pragma unroll
            for (int i = 0; i < 4; i++) acc[mt][nt][i] = 0.0f;

    const int NIT = K / 16;   // 32
    loadTiles(0, 0);

    for (int it = 0; it < NIT; it++) {
        int buf = it & 1;
        if (it + 1 < NIT) {
            loadTiles((it + 1) * 16, buf ^ 1);
            asm volatile("cp.async.wait_group 1;" ::: "memory");
        } else {
            asm volatile("cp.async.wait_group 0;" ::: "memory");
        }
        __syncthreads();

        const float* as = As[buf];
        const float* bs = Bs[buf];

        uint32_t fah[2][4], fal[2][4];
#pragma unroll
        for (int mt = 0; mt < 2; mt++) {
            int r0 = wm * 32 + mt * 16 + qr;
            int c0 = 2 * qc;
            float2 p0 = *reinterpret_cast<const float2*>(&as[r0 * APITCH + c0]);
            float2 p1 = *reinterpret_cast<const float2*>(&as[(r0 + 8) * APITCH + c0]);
            float2 p2 = *reinterpret_cast<const float2*>(&as[r0 * APITCH + c0 + 8]);
            float2 p3 = *reinterpret_cast<const float2*>(&as[(r0 + 8) * APITCH + c0 + 8]);
            split_bf2(p0.x, p0.y, fah[mt][0], fal[mt][0]);
            split_bf2(p1.x, p1.y, fah[mt][1], fal[mt][1]);
            split_bf2(p2.x, p2.y, fah[mt][2], fal[mt][2]);
            split_bf2(p3.x, p3.y, fah[mt][3], fal[mt][3]);
        }
        uint32_t fbh[4][2], fbl[4][2];
#pragma unroll
        for (int nt = 0; nt < 4; nt++) {
            int col = wn * 32 + nt * 8 + qr;
            float v0 = bs[(2 * qc) * BPITCH + col];
            float v1 = bs[(2 * qc + 1) * BPITCH + col];
            float v2 = bs[(2 * qc + 8) * BPITCH + col];
            float v3 = bs[(2 * qc + 9) * BPITCH + col];
            split_bf2(v0, v1, fbh[nt][0], fbl[nt][0]);
            split_bf2(v2, v3, fbh[nt][1], fbl[nt][1]);
        }
#pragma unroll
        for (int mt = 0; mt < 2; mt++)
#pragma unroll
            for (int nt = 0; nt < 4; nt++) {
                mma_bf16(acc[mt][nt], fah[mt], fbh[nt]);
                mma_bf16(acc[mt][nt], fah[mt], fbl[nt]);
                mma_bf16(acc[mt][nt], fal[mt], fbh[nt]);
            }
        __syncthreads();
    }

#pragma unroll
    for (int mt = 0; mt < 2; mt++) {
#pragma unroll
        for (int nt = 0; nt < 4; nt++) {
            int r  = rowBase + wm * 32 + mt * 16 + qr;
            int cc = wn * 32 + nt * 8 + qc * 2;
            if (r < M)
                *reinterpret_cast<float2*>(&g_hA[(size_t)r * HID + cc]) =
                    make_float2(acc[mt][nt][0], acc[mt][nt][1]);
            if (r + 8 < M)
                *reinterpret_cast<float2*>(&g_hA[(size_t)(r + 8) * HID + cc]) =
                    make_float2(acc[mt][nt][2], acc[mt][nt][3]);
        }
    }
}

// ------- FFMA GEMM (layer 2, K=64), row-chunked: g_hC = relu(g_hB) @ W2 -------

__global__ void __launch_bounds__(256)
k_gemm64(const float* __restrict__ B, int rowOffset, int rowEnd) {
    const int BM = 128, BN = 64, BK = 32, TM = 8, TN = 4, K = HID;
    __shared__ float As[BK][BM];
    __shared__ float Bs[BK][BN];

    const float* A = g_hB;

    int tid = threadIdx.x;
    int tx = tid & 15;
    int ty = tid >> 4;
    int rowBase = rowOffset + blockIdx.x * BM;

    float acc[TM][TN];
#pragma unroll
    for (int m = 0; m < TM; m++)
#pragma unroll
        for (int n = 0; n < TN; n++) acc[m][n] = 0.0f;

    for (int k0 = 0; k0 < K; k0 += BK) {
#pragma unroll
        for (int i = 0; i < 4; i++) {
            int idx = tid + i * 256;
            int r   = idx >> 3;
            int k4  = idx & 7;
            int grow = rowBase + r;
            float4 v = make_float4(0.f, 0.f, 0.f, 0.f);
            if (grow < rowEnd)
                v = *reinterpret_cast<const float4*>(&A[(size_t)grow * K + k0 + k4 * 4]);
            v.x = fmaxf(v.x, 0.f); v.y = fmaxf(v.y, 0.f);
            v.z = fmaxf(v.z, 0.f); v.w = fmaxf(v.w, 0.f);
            As[k4 * 4 + 0][r] = v.x;
            As[k4 * 4 + 1][r] = v.y;
            As[k4 * 4 + 2][r] = v.z;
            As[k4 * 4 + 3][r] = v.w;
        }
#pragma unroll
        for (int i = 0; i < 2; i++) {
            int idx = tid + i * 256;
            int r = idx >> 4;
            int c4 = idx & 15;
            *reinterpret_cast<float4*>(&Bs[r][c4 * 4]) =
                *reinterpret_cast<const float4*>(&B[(size_t)(k0 + r) * BN + c4 * 4]);
        }
        __syncthreads();

#pragma unroll
        for (int k = 0; k < BK; k++) {
            float a[TM], b[TN];
#pragma unroll
            for (int m = 0; m < TM; m++) a[m] = As[k][ty * TM + m];
#pragma unroll
            for (int n = 0; n < TN; n++) b[n] = Bs[k][tx * TN + n];
#pragma unroll
            for (int m = 0; m < TM; m++)
#pragma unroll
                for (int n = 0; n < TN; n++) acc[m][n] = fmaf(a[m], b[n], acc[m][n]);
        }
        __syncthreads();
    }

#pragma unroll
    for (int m = 0; m < TM; m++) {
        int grow = rowBase + ty * TM + m;
        if (grow < rowEnd) {
            float4 v = make_float4(acc[m][0], acc[m][1], acc[m][2], acc[m][3]);
            *reinterpret_cast<float4*>(&g_hC[(size_t)grow * BN + tx * TN]) = v;
        }
    }
}

// -------- pull aggregation: one warp per dst row --------
// Dynamic trip count (matches real work) + next-batch packet prefetch
// (edge-packet load latency hidden behind current batch's gathers).

template <bool FUSE_FC>
__global__ void __launch_bounds__(256)
k_pull(const float* __restrict__ bias, const float* __restrict__ Wfc,
       const float* __restrict__ bfc, float* __restrict__ out, int rowOffset) {
    int lane = threadIdx.x & 31;
    int row = rowOffset + blockIdx.x * 8 + (threadIdx.x >> 5);
    if (row >= N_NODES) return;

    const float* H = FUSE_FC ? g_hC : g_hA;

    float di = g_dinv[row];
    float c = di * di;
    const float* hr = &H[(size_t)row * HID];
    float a0 = fmaf(hr[lane],      c, bias[lane]);
    float a1 = fmaf(hr[lane + 32], c, bias[lane + 32]);

    int start = g_rowptr[row];
    int end   = g_rowptr[row + 1];

    int2 pk = make_int2(0, 0);
    if (start + lane < end) pk = g_epack[start + lane];

    for (int i = start; i < end; i += 32) {
        int n = min(32, end - i);
        int2 cur = pk;
        // prefetch next batch's packet while gathering this batch
        if (i + 32 + lane < end) pk = g_epack[i + 32 + lane];
        for (int j = 0; j < n; j++) {
            int   s  = __shfl_sync(~0u, cur.x, j);
            float nm = __int_as_float(__shfl_sync(~0u, cur.y, j));
            const float* hs = &H[(size_t)s * HID];
            a0 = fmaf(hs[lane],      nm, a0);
            a1 = fmaf(hs[lane + 32], nm, a1);
        }
    }

    if (!FUSE_FC) {
        g_hB[(size_t)row * HID + lane]      = a0;
        g_hB[(size_t)row * HID + lane + 32] = a1;
    } else {
        a0 = fmaxf(a0, 0.f);
        a1 = fmaxf(a1, 0.f);
        float res[OUT_DIM];
#pragma unroll
        for (int k = 0; k < OUT_DIM; k++) {
            float p = a0 * __ldg(&Wfc[lane * OUT_DIM + k]) +
                      a1 * __ldg(&Wfc[(lane + 32) * OUT_DIM + k]);
#pragma unroll
            for (int o = 16; o > 0; o >>= 1) p += __shfl_xor_sync(~0u, p, o);
            res[k] = p;
        }
        if (lane < OUT_DIM)
            out[(size_t)row * OUT_DIM + lane] = res[lane] + bfc[lane];
    }
}

// ---------------- launcher ----------------
// DAG: CSR-build || GEMM1 (fork/join); pull1(c) pipeline-feeds gemm64(c)
// on s1 (hC output: no aliasing with pull1's hA gathers); join; pull2+FC.

extern "C" void kernel_launch(void* const* d_in, const int* in_sizes, int n_in,
                              void* d_out, int out_size) {
    const float* x   = (const float*)d_in[0];
    const int*   ei  = (const int*)d_in[1];    // int32 (JAX x64 disabled)
    const float* ew  = (const float*)d_in[2];
    const float* W1  = (const float*)d_in[3];
    const float* b1  = (const float*)d_in[4];
    const float* W2  = (const float*)d_in[5];
    const float* b2  = (const float*)d_in[6];
    const float* Wfc = (const float*)d_in[7];
    const float* bfc = (const float*)d_in[8];
    float* out = (float*)d_out;

    static cudaStream_t s1 = nullptr;
    static cudaEvent_t evFork = nullptr, evJoin = nullptr, evG = nullptr;
    static cudaEvent_t evP[NCHUNK] = {};
    if (!s1) {
        cudaStreamCreateWithFlags(&s1, cudaStreamNonBlocking);
        cudaEventCreateWithFlags(&evFork, cudaEventDisableTiming);
        cudaEventCreateWithFlags(&evJoin, cudaEventDisableTiming);
        cudaEventCreateWithFlags(&evG, cudaEventDisableTiming);
        for (int i = 0; i < NCHUNK; i++)
            cudaEventCreateWithFlags(&evP[i], cudaEventDisableTiming);
    }

    const int T = 256;
    int gbN     = (N_NODES + T - 1) / T;
    int gbE     = (N_EDGES + T - 1) / T;
    int gbGemm  = (N_NODES + 127) / 128;
    int gbGemmC = (CHUNK + 127) / 128;
    int gbPull  = (N_NODES + 7) / 8;
    int gbPullC = (CHUNK + 7) / 8;

    // Fork: GEMM1 on s1, CSR build on the main (capture) stream.
    cudaEventRecord(evFork, 0);
    cudaStreamWaitEvent(s1, evFork, 0);
    k_gemm_bf16<<<gbGemm, T, 0, s1>>>(x, W1, IN_DIM);
    cudaEventRecord(evJoin, s1);

    k_init<<<gbN, T>>>();
    k_accum_deg<<<gbE, T>>>(ei, ew);
    k_rsqrt<<<gbN, T>>>();
    k_scan1<<<NBLK, SB>>>();
    k_scan2<<<1, 32>>>();
    k_scan3<<<NBLK, SB>>>();
    k_fill<<<gbE, T>>>(ei, ew);

    // Join: pull1 needs both hA (s1) and the CSR (main stream).
    cudaStreamWaitEvent((cudaStream_t)0, evJoin, 0);

    // Chunk pipeline: pull1(c) on stream 0 -> gemm64(c) on s1.
    for (int c = 0; c < NCHUNK; c++) {
        int r0 = c * CHUNK;
        int r1 = (c == NCHUNK - 1) ? N_NODES : (c + 1) * CHUNK;
        k_pull<false><<<gbPullC, T>>>(b1, nullptr, nullptr, nullptr, r0);
        cudaEventRecord(evP[c], 0);
        cudaStreamWaitEvent(s1, evP[c], 0);
        k_gemm64<<<gbGemmC, T, 0, s1>>>(W2, r0, r1);
    }
    cudaEventRecord(evG, s1);
    cudaStreamWaitEvent((cudaStream_t)0, evG, 0);

    // layer 2 aggregation + fused FC (reads hC)
    k_pull<true><<<gbPull, T>>>(b2, Wfc, bfc, out, 0);
}

// round 15
// speedup vs baseline: 1.0704x; 1.0621x over previous
#include <cuda_runtime.h>
#include <cuda_bf16.h>
#include <cstdint>

#define N_NODES 100000
#define N_EDGES 3200000
#define IN_DIM  512
#define HID     64
#define OUT_DIM 5

#define SB 1024
#define NBLK ((N_NODES + SB - 1) / SB)   // 98

// Scratch (allocation-free rule): __device__ globals, device-code refs only.
// Dataflow: hA =x@W1=> (pull1) => hB =relu@W2=> hA => (pull2+FC) => out
__device__ __align__(16) float g_dinv[N_NODES];
__device__ __align__(16) float g_hA[(size_t)N_NODES * HID];
__device__ __align__(16) float g_hB[(size_t)N_NODES * HID];
// CSR (dst-binned), rebuilt each launch, shared by both layers.
__device__ int  g_cnt[N_NODES];
__device__ int  g_rowptr[N_NODES + 1];
__device__ int  g_cursor[N_NODES];
__device__ int  g_bsum[NBLK];
__device__ __align__(8) int2 g_epack[N_EDGES];   // {src, bitcast(norm)}

// ---------------- degree + incoming-count ----------------

__global__ void k_init() {
    int i = blockIdx.x * blockDim.x + threadIdx.x;
    if (i < N_NODES) { g_dinv[i] = 1.0f; g_cnt[i] = 0; }
}

__global__ void k_accum_deg(const int* __restrict__ ei,
                            const float* __restrict__ ew) {
    int e = blockIdx.x * blockDim.x + threadIdx.x;
    if (e < N_EDGES) {
        int d = ei[N_EDGES + e];
        atomicAdd(&g_dinv[d], ew[e]);
        atomicAdd(&g_cnt[d], 1);
    }
}

__global__ void k_rsqrt() {
    int i = blockIdx.x * blockDim.x + threadIdx.x;
    if (i < N_NODES) g_dinv[i] = rsqrtf(g_dinv[i]);
}

// ---------------- multi-block 3-phase prefix scan ----------------

__global__ void __launch_bounds__(SB) k_scan1() {
    __shared__ int ws[32];
    int tid = threadIdx.x, lane = tid & 31, wid = tid >> 5;
    int i = blockIdx.x * SB + tid;
    int v = (i < N_NODES) ? g_cnt[i] : 0;
    int x = v;
#pragma unroll
    for (int o = 1; o < 32; o <<= 1) {
        int y = __shfl_up_sync(~0u, x, o);
        if (lane >= o) x += y;
    }
    if (lane == 31) ws[wid] = x;
    __syncthreads();
    if (wid == 0) {
        int w = ws[lane];
#pragma unroll
        for (int o = 1; o < 32; o <<= 1) {
            int y = __shfl_up_sync(~0u, w, o);
            if (lane >= o) w += y;
        }
        ws[lane] = w;
    }
    __syncthreads();
    int incl = x + (wid > 0 ? ws[wid - 1] : 0);
    if (i < N_NODES) g_rowptr[i + 1] = incl;
    if (tid == SB - 1) g_bsum[blockIdx.x] = incl;
}

__global__ void k_scan2() {
    int lane = threadIdx.x;
    int carry = 0;
    for (int base = 0; base < NBLK; base += 32) {
        int v = (base + lane < NBLK) ? g_bsum[base + lane] : 0;
        int x = v;
#pragma unroll
        for (int o = 1; o < 32; o <<= 1) {
            int y = __shfl_up_sync(~0u, x, o);
            if (lane >= o) x += y;
        }
        if (base + lane < NBLK) g_bsum[base + lane] = x - v + carry;
        carry += __shfl_sync(~0u, x, 31);
    }
}

__global__ void __launch_bounds__(SB) k_scan3() {
    int i = blockIdx.x * SB + threadIdx.x;
    if (i >= N_NODES) return;
    int off = g_bsum[i >> 10];
    int r = g_rowptr[i + 1] + off;
    g_rowptr[i + 1] = r;
    g_cursor[i] = r - g_cnt[i];
    if (i == 0) g_rowptr[0] = 0;
}

// ---------------- CSR fill ----------------

__global__ void k_fill(const int* __restrict__ ei, const float* __restrict__ ew) {
    int e = blockIdx.x * blockDim.x + threadIdx.x;
    if (e >= N_EDGES) return;
    int s = ei[e];
    int d = ei[N_EDGES + e];
    float nm = g_dinv[s] * ew[e] * g_dinv[d];
    int pos = atomicAdd(&g_cursor[d], 1);
    g_epack[pos] = make_int2(s, __float_as_int(nm));
}

// ---------------- bf16 split helpers ----------------

__device__ __forceinline__ void split_bf2(float v0, float v1,
                                          uint32_t& h, uint32_t& l) {
    __nv_bfloat16 b0 = __float2bfloat16(v0);
    __nv_bfloat16 b1 = __float2bfloat16(v1);
    __nv_bfloat162 hp = __halves2bfloat162(b0, b1);   // b0 in low 16 bits
    h = *reinterpret_cast<uint32_t*>(&hp);
    float r0 = v0 - __bfloat162float(b0);
    float r1 = v1 - __bfloat162float(b1);
    asm("cvt.rn.bf16x2.f32 %0, %1, %2;" : "=r"(l) : "f"(r1), "f"(r0));
}

__device__ __forceinline__ void mma_bf16(float* c, const uint32_t* a, const uint32_t* b) {
    asm volatile(
        "mma.sync.aligned.m16n8k16.row.col.f32.bf16.bf16.f32 "
        "{%0,%1,%2,%3}, {%4,%5,%6,%7}, {%8,%9}, {%0,%1,%2,%3};"
        : "+f"(c[0]), "+f"(c[1]), "+f"(c[2]), "+f"(c[3])
        : "r"(a[0]), "r"(a[1]), "r"(a[2]), "r"(a[3]), "r"(b[0]), "r"(b[1]));
}

__device__ __forceinline__ void cp16(uint32_t dst, const void* src, bool valid) {
    asm volatile("cp.async.cg.shared.global [%0], [%1], 16, %2;"
                 :: "r"(dst), "l"(src), "r"(valid ? 16 : 0) : "memory");
}

// ------- 3xBF16 tensor-core GEMM (layer 1): g_hA = x @ W1, K=512 -------

#define APITCH 20
#define BPITCH 72

__global__ void __launch_bounds__(256)
k_gemm_bf16(const float* __restrict__ A, const float* __restrict__ B, int K) {
    __shared__ float As[2][128 * APITCH];
    __shared__ float Bs[2][16 * BPITCH];

    const int M = N_NODES;
    int tid  = threadIdx.x;
    int wid  = tid >> 5;
    int lane = tid & 31;
    int wm = wid >> 1, wn = wid & 1;
    int qr = lane >> 2, qc = lane & 3;
    int rowBase = blockIdx.x * 128;

    int ar0 = tid >> 2,         ac0 = (tid & 3) * 4;
    int ar1 = (tid >> 2) + 64,  ac1 = ac0;
    int brr = tid >> 4,         bcc = (tid & 15) * 4;

    uint32_t sA0[2], sA1[2], sB0[2];
#pragma unroll
    for (int b = 0; b < 2; b++) {
        sA0[b] = (uint32_t)__cvta_generic_to_shared(&As[b][ar0 * APITCH + ac0]);
        sA1[b] = (uint32_t)__cvta_generic_to_shared(&As[b][ar1 * APITCH + ac1]);
        sB0[b] = (uint32_t)__cvta_generic_to_shared(&Bs[b][brr * BPITCH + bcc]);
    }

    auto loadTiles = [&](int k0, int buf) {
        int g0 = rowBase + ar0, g1 = rowBase + ar1;
        bool v0 = g0 < M, v1 = g1 < M;
        cp16(sA0[buf], &A[(size_t)(v0 ? g0 : 0) * K + k0 + ac0], v0);
        cp16(sA1[buf], &A[(size_t)(v1 ? g1 : 0) * K + k0 + ac1], v1);
        cp16(sB0[buf], &B[(size_t)(k0 + brr) * HID + bcc], true);
        asm volatile("cp.async.commit_group;" ::: "memory");
    };

    float acc[2][4][4];
#pragma unroll
    for (int mt = 0; mt < 2; mt++)
#pragma unroll
        for (int nt = 0; nt < 4; nt++)
#pragma unroll
            for (int i = 0; i < 4; i++) acc[mt][nt][i] = 0.0f;

    const int NIT = K / 16;   // 32
    loadTiles(0, 0);

    for (int it = 0; it < NIT; it++) {
        int buf = it & 1;
        if (it + 1 < NIT) {
            loadTiles((it + 1) * 16, buf ^ 1);
            asm volatile("cp.async.wait_group 1;" ::: "memory");
        } else {
            asm volatile("cp.async.wait_group 0;" ::: "memory");
        }
        __syncthreads();

        const float* as = As[buf];
        const float* bs = Bs[buf];

        uint32_t fah[2][4], fal[2][4];
#pragma unroll
        for (int mt = 0; mt < 2; mt++) {
            int r0 = wm * 32 + mt * 16 + qr;
            int c0 = 2 * qc;
            float2 p0 = *reinterpret_cast<const float2*>(&as[r0 * APITCH + c0]);
            float2 p1 = *reinterpret_cast<const float2*>(&as[(r0 + 8) * APITCH + c0]);
            float2 p2 = *reinterpret_cast<const float2*>(&as[r0 * APITCH + c0 + 8]);
            float2 p3 = *reinterpret_cast<const float2*>(&as[(r0 + 8) * APITCH + c0 + 8]);
            split_bf2(p0.x, p0.y, fah[mt][0], fal[mt][0]);
            split_bf2(p1.x, p1.y, fah[mt][1], fal[mt][1]);
            split_bf2(p2.x, p2.y, fah[mt][2], fal[mt][2]);
            split_bf2(p3.x, p3.y, fah[mt][3], fal[mt][3]);
        }
        uint32_t fbh[4][2], fbl[4][2];
#pragma unroll
        for (int nt = 0; nt < 4; nt++) {
            int col = wn * 32 + nt * 8 + qr;
            float v0 = bs[(2 * qc) * BPITCH + col];
            float v1 = bs[(2 * qc + 1) * BPITCH + col];
            float v2 = bs[(2 * qc + 8) * BPITCH + col];
            float v3 = bs[(2 * qc + 9) * BPITCH + col];
            split_bf2(v0, v1, fbh[nt][0], fbl[nt][0]);
            split_bf2(v2, v3, fbh[nt][1], fbl[nt][1]);
        }
#pragma unroll
        for (int mt = 0; mt < 2; mt++)
#pragma unroll
            for (int nt = 0; nt < 4; nt++) {
                mma_bf16(acc[mt][nt], fah[mt], fbh[nt]);
                mma_bf16(acc[mt][nt], fah[mt], fbl[nt]);
                mma_bf16(acc[mt][nt], fal[mt], fbh[nt]);
            }
        __syncthreads();
    }

#pragma unroll
    for (int mt = 0; mt < 2; mt++) {
#pragma unroll
        for (int nt = 0; nt < 4; nt++) {
            int r  = rowBase + wm * 32 + mt * 16 + qr;
            int cc = wn * 32 + nt * 8 + qc * 2;
            if (r < M)
                *reinterpret_cast<float2*>(&g_hA[(size_t)r * HID + cc]) =
                    make_float2(acc[mt][nt][0], acc[mt][nt][1]);
            if (r + 8 < M)
                *reinterpret_cast<float2*>(&g_hA[(size_t)(r + 8) * HID + cc]) =
                    make_float2(acc[mt][nt][2], acc[mt][nt][3]);
        }
    }
}

// ------- FFMA GEMM (layer 2, K=64): g_hA = relu(g_hB) @ W2 -------

__global__ void __launch_bounds__(256)
k_gemm64(const float* __restrict__ B) {
    const int BM = 128, BN = 64, BK = 32, TM = 8, TN = 4, K = HID;
    __shared__ float As[BK][BM];
    __shared__ float Bs[BK][BN];

    const float* A = g_hB;
    const int M = N_NODES;

    int tid = threadIdx.x;
    int tx = tid & 15;
    int ty = tid >> 4;
    int rowBase = blockIdx.x * BM;

    float acc[TM][TN];
#pragma unroll
    for (int m = 0; m < TM; m++)
#pragma unroll
        for (int n = 0; n < TN; n++) acc[m][n] = 0.0f;

    for (int k0 = 0; k0 < K; k0 += BK) {
#pragma unroll
        for (int i = 0; i < 4; i++) {
            int idx = tid + i * 256;
            int r   = idx >> 3;
            int k4  = idx & 7;
            int grow = rowBase + r;
            float4 v = make_float4(0.f, 0.f, 0.f, 0.f);
            if (grow < M)
                v = *reinterpret_cast<const float4*>(&A[(size_t)grow * K + k0 + k4 * 4]);
            v.x = fmaxf(v.x, 0.f); v.y = fmaxf(v.y, 0.f);
            v.z = fmaxf(v.z, 0.f); v.w = fmaxf(v.w, 0.f);
            As[k4 * 4 + 0][r] = v.x;
            As[k4 * 4 + 1][r] = v.y;
            As[k4 * 4 + 2][r] = v.z;
            As[k4 * 4 + 3][r] = v.w;
        }
#pragma unroll
        for (int i = 0; i < 2; i++) {
            int idx = tid + i * 256;
            int r = idx >> 4;
            int c4 = idx & 15;
            *reinterpret_cast<float4*>(&Bs[r][c4 * 4]) =
                *reinterpret_cast<const float4*>(&B[(size_t)(k0 + r) * BN + c4 * 4]);
        }
        __syncthreads();

#pragma unroll
        for (int k = 0; k < BK; k++) {
            float a[TM], b[TN];
#pragma unroll
            for (int m = 0; m < TM; m++) a[m] = As[k][ty * TM + m];
#pragma unroll
            for (int n = 0; n < TN; n++) b[n] = Bs[k][tx * TN + n];
#pragma unroll
            for (int m = 0; m < TM; m++)
#pragma unroll
                for (int n = 0; n < TN; n++) acc[m][n] = fmaf(a[m], b[n], acc[m][n]);
        }
        __syncthreads();
    }

#pragma unroll
    for (int m = 0; m < TM; m++) {
        int grow = rowBase + ty * TM + m;
        if (grow < M) {
            float4 v = make_float4(acc[m][0], acc[m][1], acc[m][2], acc[m][3]);
            *reinterpret_cast<float4*>(&g_hA[(size_t)grow * BN + tx * TN]) = v;
        }
    }
}

// -------- pull aggregation: one warp per dst row --------
// Dynamic trip count + next-batch packet prefetch.
// pull1 (FUSE_FC=false): reads g_hA, writes g_hB.
// pull2 (FUSE_FC=true):  reads g_hA (layer-2 features), ReLU+FC -> out.

template <bool FUSE_FC>
__global__ void __launch_bounds__(256)
k_pull(const float* __restrict__ bias, const float* __restrict__ Wfc,
       const float* __restrict__ bfc, float* __restrict__ out) {
    int lane = threadIdx.x & 31;
    int row = blockIdx.x * 8 + (threadIdx.x >> 5);
    if (row >= N_NODES) return;

    const float* H = g_hA;

    float di = g_dinv[row];
    float c = di * di;
    const float* hr = &H[(size_t)row * HID];
    float a0 = fmaf(hr[lane],      c, bias[lane]);
    float a1 = fmaf(hr[lane + 32], c, bias[lane + 32]);

    int start = g_rowptr[row];
    int end   = g_rowptr[row + 1];

    int2 pk = make_int2(0, 0);
    if (start + lane < end) pk = g_epack[start + lane];

    for (int i = start; i < end; i += 32) {
        int n = min(32, end - i);
        int2 cur = pk;
        // prefetch next batch's packet while gathering this batch
        if (i + 32 + lane < end) pk = g_epack[i + 32 + lane];
        for (int j = 0; j < n; j++) {
            int   s  = __shfl_sync(~0u, cur.x, j);
            float nm = __int_as_float(__shfl_sync(~0u, cur.y, j));
            const float* hs = &H[(size_t)s * HID];
            a0 = fmaf(hs[lane],      nm, a0);
            a1 = fmaf(hs[lane + 32], nm, a1);
        }
    }

    if (!FUSE_FC) {
        g_hB[(size_t)row * HID + lane]      = a0;
        g_hB[(size_t)row * HID + lane + 32] = a1;
    } else {
        a0 = fmaxf(a0, 0.f);
        a1 = fmaxf(a1, 0.f);
        float res[OUT_DIM];
#pragma unroll
        for (int k = 0; k < OUT_DIM; k++) {
            float p = a0 * __ldg(&Wfc[lane * OUT_DIM + k]) +
                      a1 * __ldg(&Wfc[(lane + 32) * OUT_DIM + k]);
#pragma unroll
            for (int o = 16; o > 0; o >>= 1) p += __shfl_xor_sync(~0u, p, o);
            res[k] = p;
        }
        if (lane < OUT_DIM)
            out[(size_t)row * OUT_DIM + lane] = res[lane] + bfc[lane];
    }
}

// ---------------- launcher ----------------
// R11 structure (measured best): CSR-build || GEMM1 fork/join; then
// pull1 -> gemm64 -> pull2+FC sequentially on the main stream.

extern "C" void kernel_launch(void* const* d_in, const int* in_sizes, int n_in,
                              void* d_out, int out_size) {
    const float* x   = (const float*)d_in[0];
    const int*   ei  = (const int*)d_in[1];    // int32 (JAX x64 disabled)
    const float* ew  = (const float*)d_in[2];
    const float* W1  = (const float*)d_in[3];
    const float* b1  = (const float*)d_in[4];
    const float* W2  = (const float*)d_in[5];
    const float* b2  = (const float*)d_in[6];
    const float* Wfc = (const float*)d_in[7];
    const float* bfc = (const float*)d_in[8];
    float* out = (float*)d_out;

    static cudaStream_t s1 = nullptr;
    static cudaEvent_t evFork = nullptr, evJoin = nullptr;
    if (!s1) {
        cudaStreamCreateWithFlags(&s1, cudaStreamNonBlocking);
        cudaEventCreateWithFlags(&evFork, cudaEventDisableTiming);
        cudaEventCreateWithFlags(&evJoin, cudaEventDisableTiming);
    }

    const int T = 256;
    int gbN    = (N_NODES + T - 1) / T;
    int gbE    = (N_EDGES + T - 1) / T;
    int gbGemm = (N_NODES + 127) / 128;
    int gbPull = (N_NODES + 7) / 8;

    // Fork: GEMM1 on s1, CSR build on the main (capture) stream.
    cudaEventRecord(evFork, 0);
    cudaStreamWaitEvent(s1, evFork, 0);
    k_gemm_bf16<<<gbGemm, T, 0, s1>>>(x, W1, IN_DIM);
    cudaEventRecord(evJoin, s1);

    k_init<<<gbN, T>>>();
    k_accum_deg<<<gbE, T>>>(ei, ew);
    k_rsqrt<<<gbN, T>>>();
    k_scan1<<<NBLK, SB>>>();
    k_scan2<<<1, 32>>>();
    k_scan3<<<NBLK, SB>>>();
    k_fill<<<gbE, T>>>(ei, ew);

    // Join: pull1 needs both hA (s1) and the CSR (main stream).
    cudaStreamWaitEvent((cudaStream_t)0, evJoin, 0);

    // layer 1 aggregation, layer 2 transform, layer 2 aggregation + FC
    k_pull<false><<<gbPull, T>>>(b1, nullptr, nullptr, nullptr);
    k_gemm64<<<gbGemm, T>>>(W2);
    k_pull<true><<<gbPull, T>>>(b2, Wfc, bfc, out);
}

// round 16
// speedup vs baseline: 1.1233x; 1.0495x over previous
#include <cuda_runtime.h>
#include <cuda_bf16.h>
#include <cstdint>

#define N_NODES 100000
#define N_EDGES 3200000
#define IN_DIM  512
#define HID     64
#define OUT_DIM 5

#define SB 1024
#define NBLK ((N_NODES + SB - 1) / SB)   // 98

// Scratch (allocation-free rule): __device__ globals, device-code refs only.
// Dataflow: hA =x@W1=> (pull1) => hB =relu@W2=> hA => (pull2+FC) => out
__device__ __align__(16) float g_dinv[N_NODES];
__device__ __align__(16) float g_hA[(size_t)N_NODES * HID];
__device__ __align__(16) float g_hB[(size_t)N_NODES * HID];
// CSR (dst-binned), rebuilt each launch, shared by both layers.
__device__ int  g_cnt[N_NODES];
__device__ int  g_rowptr[N_NODES + 1];
__device__ int  g_cursor[N_NODES];
__device__ int  g_bsum[NBLK];
__device__ __align__(8) int2 g_epack[N_EDGES];   // {src, bitcast(norm)}

// ---------------- degree + incoming-count ----------------

__global__ void k_init() {
    int i = blockIdx.x * blockDim.x + threadIdx.x;
    if (i < N_NODES) { g_dinv[i] = 1.0f; g_cnt[i] = 0; }
}

__global__ void k_accum_deg(const int* __restrict__ ei,
                            const float* __restrict__ ew) {
    int e = blockIdx.x * blockDim.x + threadIdx.x;
    if (e < N_EDGES) {
        int d = ei[N_EDGES + e];
        atomicAdd(&g_dinv[d], ew[e]);
        atomicAdd(&g_cnt[d], 1);
    }
}

__global__ void k_rsqrt() {
    int i = blockIdx.x * blockDim.x + threadIdx.x;
    if (i < N_NODES) g_dinv[i] = rsqrtf(g_dinv[i]);
}

// ---------------- multi-block 3-phase prefix scan ----------------

__global__ void __launch_bounds__(SB) k_scan1() {
    __shared__ int ws[32];
    int tid = threadIdx.x, lane = tid & 31, wid = tid >> 5;
    int i = blockIdx.x * SB + tid;
    int v = (i < N_NODES) ? g_cnt[i] : 0;
    int x = v;
#pragma unroll
    for (int o = 1; o < 32; o <<= 1) {
        int y = __shfl_up_sync(~0u, x, o);
        if (lane >= o) x += y;
    }
    if (lane == 31) ws[wid] = x;
    __syncthreads();
    if (wid == 0) {
        int w = ws[lane];
#pragma unroll
        for (int o = 1; o < 32; o <<= 1) {
            int y = __shfl_up_sync(~0u, w, o);
            if (lane >= o) w += y;
        }
        ws[lane] = w;
    }
    __syncthreads();
    int incl = x + (wid > 0 ? ws[wid - 1] : 0);
    if (i < N_NODES) g_rowptr[i + 1] = incl;
    if (tid == SB - 1) g_bsum[blockIdx.x] = incl;
}

__global__ void k_scan2() {
    int lane = threadIdx.x;
    int carry = 0;
    for (int base = 0; base < NBLK; base += 32) {
        int v = (base + lane < NBLK) ? g_bsum[base + lane] : 0;
        int x = v;
#pragma unroll
        for (int o = 1; o < 32; o <<= 1) {
            int y = __shfl_up_sync(~0u, x, o);
            if (lane >= o) x += y;
        }
        if (base + lane < NBLK) g_bsum[base + lane] = x - v + carry;
        carry += __shfl_sync(~0u, x, 31);
    }
}

__global__ void __launch_bounds__(SB) k_scan3() {
    int i = blockIdx.x * SB + threadIdx.x;
    if (i >= N_NODES) return;
    int off = g_bsum[i >> 10];
    int r = g_rowptr[i + 1] + off;
    g_rowptr[i + 1] = r;
    g_cursor[i] = r - g_cnt[i];
    if (i == 0) g_rowptr[0] = 0;
}

// ---------------- CSR fill ----------------

__global__ void k_fill(const int* __restrict__ ei, const float* __restrict__ ew) {
    int e = blockIdx.x * blockDim.x + threadIdx.x;
    if (e >= N_EDGES) return;
    int s = ei[e];
    int d = ei[N_EDGES + e];
    float nm = g_dinv[s] * ew[e] * g_dinv[d];
    int pos = atomicAdd(&g_cursor[d], 1);
    g_epack[pos] = make_int2(s, __float_as_int(nm));
}

// ---------------- bf16 split helpers ----------------

__device__ __forceinline__ void split_bf2(float v0, float v1,
                                          uint32_t& h, uint32_t& l) {
    __nv_bfloat16 b0 = __float2bfloat16(v0);
    __nv_bfloat16 b1 = __float2bfloat16(v1);
    __nv_bfloat162 hp = __halves2bfloat162(b0, b1);   // b0 in low 16 bits
    h = *reinterpret_cast<uint32_t*>(&hp);
    float r0 = v0 - __bfloat162float(b0);
    float r1 = v1 - __bfloat162float(b1);
    asm("cvt.rn.bf16x2.f32 %0, %1, %2;" : "=r"(l) : "f"(r1), "f"(r0));
}

__device__ __forceinline__ void mma_bf16(float* c, const uint32_t* a, const uint32_t* b) {
    asm volatile(
        "mma.sync.aligned.m16n8k16.row.col.f32.bf16.bf16.f32 "
        "{%0,%1,%2,%3}, {%4,%5,%6,%7}, {%8,%9}, {%0,%1,%2,%3};"
        : "+f"(c[0]), "+f"(c[1]), "+f"(c[2]), "+f"(c[3])
        : "r"(a[0]), "r"(a[1]), "r"(a[2]), "r"(a[3]), "r"(b[0]), "r"(b[1]));
}

__device__ __forceinline__ void cp16(uint32_t dst, const void* src, bool valid) {
    asm volatile("cp.async.cg.shared.global [%0], [%1], 16, %2;"
                 :: "r"(dst), "l"(src), "r"(valid ? 16 : 0) : "memory");
}

// ------- 3xBF16 tensor-core GEMM (layer 1): g_hA = x @ W1, K=512 -------

#define APITCH 20
#define BPITCH 72

__global__ void __launch_bounds__(256)
k_gemm_bf16(const float* __restrict__ A, const float* __restrict__ B, int K) {
    __shared__ float As[2][128 * APITCH];
    __shared__ float Bs[2][16 * BPITCH];

    const int M = N_NODES;
    int tid  = threadIdx.x;
    int wid  = tid >> 5;
    int lane = tid & 31;
    int wm = wid >> 1, wn = wid & 1;
    int qr = lane >> 2, qc = lane & 3;
    int rowBase = blockIdx.x * 128;

    int ar0 = tid >> 2,         ac0 = (tid & 3) * 4;
    int ar1 = (tid >> 2) + 64,  ac1 = ac0;
    int brr = tid >> 4,         bcc = (tid & 15) * 4;

    uint32_t sA0[2], sA1[2], sB0[2];
#pragma unroll
    for (int b = 0; b < 2; b++) {
        sA0[b] = (uint32_t)__cvta_generic_to_shared(&As[b][ar0 * APITCH + ac0]);
        sA1[b] = (uint32_t)__cvta_generic_to_shared(&As[b][ar1 * APITCH + ac1]);
        sB0[b] = (uint32_t)__cvta_generic_to_shared(&Bs[b][brr * BPITCH + bcc]);
    }

    auto loadTiles = [&](int k0, int buf) {
        int g0 = rowBase + ar0, g1 = rowBase + ar1;
        bool v0 = g0 < M, v1 = g1 < M;
        cp16(sA0[buf], &A[(size_t)(v0 ? g0 : 0) * K + k0 + ac0], v0);
        cp16(sA1[buf], &A[(size_t)(v1 ? g1 : 0) * K + k0 + ac1], v1);
        cp16(sB0[buf], &B[(size_t)(k0 + brr) * HID + bcc], true);
        asm volatile("cp.async.commit_group;" ::: "memory");
    };

    float acc[2][4][4];
#pragma unroll
    for (int mt = 0; mt < 2; mt++)
#pragma unroll
        for (int nt = 0; nt < 4; nt++)
#pragma unroll
            for (int i = 0; i < 4; i++) acc[mt][nt][i] = 0.0f;

    const int NIT = K / 16;   // 32
    loadTiles(0, 0);

    for (int it = 0; it < NIT; it++) {
        int buf = it & 1;
        if (it + 1 < NIT) {
            loadTiles((it + 1) * 16, buf ^ 1);
            asm volatile("cp.async.wait_group 1;" ::: "memory");
        } else {
            asm volatile("cp.async.wait_group 0;" ::: "memory");
        }
        __syncthreads();

        const float* as = As[buf];
        const float* bs = Bs[buf];

        uint32_t fah[2][4], fal[2][4];
#pragma unroll
        for (int mt = 0; mt < 2; mt++) {
            int r0 = wm * 32 + mt * 16 + qr;
            int c0 = 2 * qc;
            float2 p0 = *reinterpret_cast<const float2*>(&as[r0 * APITCH + c0]);
            float2 p1 = *reinterpret_cast<const float2*>(&as[(r0 + 8) * APITCH + c0]);
            float2 p2 = *reinterpret_cast<const float2*>(&as[r0 * APITCH + c0 + 8]);
            float2 p3 = *reinterpret_cast<const float2*>(&as[(r0 + 8) * APITCH + c0 + 8]);
            split_bf2(p0.x, p0.y, fah[mt][0], fal[mt][0]);
            split_bf2(p1.x, p1.y, fah[mt][1], fal[mt][1]);
            split_bf2(p2.x, p2.y, fah[mt][2], fal[mt][2]);
            split_bf2(p3.x, p3.y, fah[mt][3], fal[mt][3]);
        }
        uint32_t fbh[4][2], fbl[4][2];
#pragma unroll
        for (int nt = 0; nt < 4; nt++) {
            int col = wn * 32 + nt * 8 + qr;
            float v0 = bs[(2 * qc) * BPITCH + col];
            float v1 = bs[(2 * qc + 1) * BPITCH + col];
            float v2 = bs[(2 * qc + 8) * BPITCH + col];
            float v3 = bs[(2 * qc + 9) * BPITCH + col];
            split_bf2(v0, v1, fbh[nt][0], fbl[nt][0]);
            split_bf2(v2, v3, fbh[nt][1], fbl[nt][1]);
        }
#pragma unroll
        for (int mt = 0; mt < 2; mt++)
#pragma unroll
            for (int nt = 0; nt < 4; nt++) {
                mma_bf16(acc[mt][nt], fah[mt], fbh[nt]);
                mma_bf16(acc[mt][nt], fah[mt], fbl[nt]);
                mma_bf16(acc[mt][nt], fal[mt], fbh[nt]);
            }
        __syncthreads();
    }

#pragma unroll
    for (int mt = 0; mt < 2; mt++) {
#pragma unroll
        for (int nt = 0; nt < 4; nt++) {
            int r  = rowBase + wm * 32 + mt * 16 + qr;
            int cc = wn * 32 + nt * 8 + qc * 2;
            if (r < M)
                *reinterpret_cast<float2*>(&g_hA[(size_t)r * HID + cc]) =
                    make_float2(acc[mt][nt][0], acc[mt][nt][1]);
            if (r + 8 < M)
                *reinterpret_cast<float2*>(&g_hA[(size_t)(r + 8) * HID + cc]) =
                    make_float2(acc[mt][nt][2], acc[mt][nt][3]);
        }
    }
}

// ------- FFMA GEMM (layer 2, K=64): g_hA = relu(g_hB) @ W2 -------

__global__ void __launch_bounds__(256)
k_gemm64(const float* __restrict__ B) {
    const int BM = 128, BN = 64, BK = 32, TM = 8, TN = 4, K = HID;
    __shared__ float As[BK][BM];
    __shared__ float Bs[BK][BN];

    const float* A = g_hB;
    const int M = N_NODES;

    int tid = threadIdx.x;
    int tx = tid & 15;
    int ty = tid >> 4;
    int rowBase = blockIdx.x * BM;

    float acc[TM][TN];
#pragma unroll
    for (int m = 0; m < TM; m++)
#pragma unroll
        for (int n = 0; n < TN; n++) acc[m][n] = 0.0f;

    for (int k0 = 0; k0 < K; k0 += BK) {
#pragma unroll
        for (int i = 0; i < 4; i++) {
            int idx = tid + i * 256;
            int r   = idx >> 3;
            int k4  = idx & 7;
            int grow = rowBase + r;
            float4 v = make_float4(0.f, 0.f, 0.f, 0.f);
            if (grow < M)
                v = *reinterpret_cast<const float4*>(&A[(size_t)grow * K + k0 + k4 * 4]);
            v.x = fmaxf(v.x, 0.f); v.y = fmaxf(v.y, 0.f);
            v.z = fmaxf(v.z, 0.f); v.w = fmaxf(v.w, 0.f);
            As[k4 * 4 + 0][r] = v.x;
            As[k4 * 4 + 1][r] = v.y;
            As[k4 * 4 + 2][r] = v.z;
            As[k4 * 4 + 3][r] = v.w;
        }
#pragma unroll
        for (int i = 0; i < 2; i++) {
            int idx = tid + i * 256;
            int r = idx >> 4;
            int c4 = idx & 15;
            *reinterpret_cast<float4*>(&Bs[r][c4 * 4]) =
                *reinterpret_cast<const float4*>(&B[(size_t)(k0 + r) * BN + c4 * 4]);
        }
        __syncthreads();

#pragma unroll
        for (int k = 0; k < BK; k++) {
            float a[TM], b[TN];
#pragma unroll
            for (int m = 0; m < TM; m++) a[m] = As[k][ty * TM + m];
#pragma unroll
            for (int n = 0; n < TN; n++) b[n] = Bs[k][tx * TN + n];
#pragma unroll
            for (int m = 0; m < TM; m++)
#pragma unroll
                for (int n = 0; n < TN; n++) acc[m][n] = fmaf(a[m], b[n], acc[m][n]);
        }
        __syncthreads();
    }

#pragma unroll
    for (int m = 0; m < TM; m++) {
        int grow = rowBase + ty * TM + m;
        if (grow < M) {
            float4 v = make_float4(acc[m][0], acc[m][1], acc[m][2], acc[m][3]);
            *reinterpret_cast<float4*>(&g_hA[(size_t)grow * BN + tx * TN]) = v;
        }
    }
}

// -------- pull aggregation: one warp per dst row (R11 measured-best form) --------
// pull1 (FUSE_FC=false): reads g_hA, writes g_hB.
// pull2 (FUSE_FC=true):  reads g_hA (layer-2 features), ReLU+FC -> out.

template <bool FUSE_FC>
__global__ void __launch_bounds__(256)
k_pull(const float* __restrict__ bias, const float* __restrict__ Wfc,
       const float* __restrict__ bfc, float* __restrict__ out) {
    int lane = threadIdx.x & 31;
    int row = blockIdx.x * 8 + (threadIdx.x >> 5);
    if (row >= N_NODES) return;

    const float* H = g_hA;

    float di = g_dinv[row];
    float c = di * di;
    const float* hr = &H[(size_t)row * HID];
    float a0 = fmaf(hr[lane],      c, bias[lane]);
    float a1 = fmaf(hr[lane + 32], c, bias[lane + 32]);

    int start = g_rowptr[row];
    int end   = g_rowptr[row + 1];
    for (int i = start; i < end; i += 32) {
        int n = min(32, end - i);
        int2 pk = make_int2(0, 0);
        if (i + lane < end) pk = g_epack[i + lane];
        for (int j = 0; j < n; j++) {
            int   s  = __shfl_sync(~0u, pk.x, j);
            float nm = __int_as_float(__shfl_sync(~0u, pk.y, j));
            const float* hs = &H[(size_t)s * HID];
            a0 = fmaf(hs[lane],      nm, a0);
            a1 = fmaf(hs[lane + 32], nm, a1);
        }
    }

    if (!FUSE_FC) {
        g_hB[(size_t)row * HID + lane]      = a0;
        g_hB[(size_t)row * HID + lane + 32] = a1;
    } else {
        a0 = fmaxf(a0, 0.f);
        a1 = fmaxf(a1, 0.f);
        float res[OUT_DIM];
#pragma unroll
        for (int k = 0; k < OUT_DIM; k++) {
            float p = a0 * __ldg(&Wfc[lane * OUT_DIM + k]) +
                      a1 * __ldg(&Wfc[(lane + 32) * OUT_DIM + k]);
#pragma unroll
            for (int o = 16; o > 0; o >>= 1) p += __shfl_xor_sync(~0u, p, o);
            res[k] = p;
        }
        if (lane < OUT_DIM)
            out[(size_t)row * OUT_DIM + lane] = res[lane] + bfc[lane];
    }
}

// ---------------- launcher ----------------
// R11 structure (measured best): CSR-build || GEMM1 fork/join; then
// pull1 -> gemm64 -> pull2+FC sequentially on the main stream.

extern "C" void kernel_launch(void* const* d_in, const int* in_sizes, int n_in,
                              void* d_out, int out_size) {
    const float* x   = (const float*)d_in[0];
    const int*   ei  = (const int*)d_in[1];    // int32 (JAX x64 disabled)
    const float* ew  = (const float*)d_in[2];
    const float* W1  = (const float*)d_in[3];
    const float* b1  = (const float*)d_in[4];
    const float* W2  = (const float*)d_in[5];
    const float* b2  = (const float*)d_in[6];
    const float* Wfc = (const float*)d_in[7];
    const float* bfc = (const float*)d_in[8];
    float* out = (float*)d_out;

    static cudaStream_t s1 = nullptr;
    static cudaEvent_t evFork = nullptr, evJoin = nullptr;
    if (!s1) {
        cudaStreamCreateWithFlags(&s1, cudaStreamNonBlocking);
        cudaEventCreateWithFlags(&evFork, cudaEventDisableTiming);
        cudaEventCreateWithFlags(&evJoin, cudaEventDisableTiming);
    }

    const int T = 256;
    int gbN    = (N_NODES + T - 1) / T;
    int gbE    = (N_EDGES + T - 1) / T;
    int gbGemm = (N_NODES + 127) / 128;
    int gbPull = (N_NODES + 7) / 8;

    // Fork: GEMM1 on s1, CSR build on the main (capture) stream.
    cudaEventRecord(evFork, 0);
    cudaStreamWaitEvent(s1, evFork, 0);
    k_gemm_bf16<<<gbGemm, T, 0, s1>>>(x, W1, IN_DIM);
    cudaEventRecord(evJoin, s1);

    k_init<<<gbN, T>>>();
    k_accum_deg<<<gbE, T>>>(ei, ew);
    k_rsqrt<<<gbN, T>>>();
    k_scan1<<<NBLK, SB>>>();
    k_scan2<<<1, 32>>>();
    k_scan3<<<NBLK, SB>>>();
    k_fill<<<gbE, T>>>(ei, ew);

    // Join: pull1 needs both hA (s1) and the CSR (main stream).
    cudaStreamWaitEvent((cudaStream_t)0, evJoin, 0);

    // layer 1 aggregation, layer 2 transform, layer 2 aggregation + FC
    k_pull<false><<<gbPull, T>>>(b1, nullptr, nullptr, nullptr);
    k_gemm64<<<gbGemm, T>>>(W2);
    k_pull<true><<<gbPull, T>>>(b2, Wfc, bfc, out);
}